// round 11
// baseline (speedup 1.0000x reference)
#include <cuda_runtime.h>
#include <math.h>

// QuanvolutionHybrid, reduced: only feats[:,0] (patch 0, wire0 <Z>) feeds the
// FC stage. Direct 4-qubit sim, 4 threads/sample, warp-autonomous blocks (R10).
// CNOT rings removed via GF(2) conjugation (masks validated R8). NEW in R11:
//  - Layer 0 folded into embedding: state after L0 is a product of per-wire
//    spinors u_w = Rot_w RX(th_w)|0>  (L0 gates are unconjugated single-wire)
//  - final gate (idx 15, mu=2) dropped: preserves <Z0> measurement sectors
//  - gate 14 folded into measurement: pair term K(|ai|^2-|aj|^2)+2Re(W ai* aj)
// Gate phase: 10 stages (gates 4..13). FC tail collapsed to
// q = alpha*cos(ez)+beta*sin(ez) (validated R9).

#define SHX(v, m) __shfl_xor_sync(0xffffffffu, (v), (m))
#define SH4(v, l) __shfl_sync(0xffffffffu, (v), (l), 4)

__device__ __forceinline__ void rot_mat_fast(float phi, float theta, float omega, float4* m) {
    // PennyLane Rot(phi,theta,omega) = RZ(omega) RY(theta) RZ(phi)
    float ct, st, ca, sa, cb, sb;
    __sincosf(0.5f * theta, &st, &ct);
    __sincosf(0.5f * (phi + omega), &sa, &ca);
    __sincosf(0.5f * (phi - omega), &sb, &cb);
    m[0] = make_float4( ct * ca, -ct * sa, -st * cb, -st * sb);  // m00, m01
    m[1] = make_float4( st * cb, -st * sb,  ct * ca,  ct * sa);  // m10, m11
}

// Conjugated two-level rotation (masks validated R8).
#define GSLOT(T, GM, TM, SG, ST) {                                            \
    float apr = ar[(T) ^ (TM)], api = ai[(T) ^ (TM)];                         \
    if ((GM) != 0) { apr = SHX(apr, (GM)); api = SHX(api, (GM)); }            \
    const int side = pg ^ ((((ST) >> 1) & ((T) >> 1)) ^ ((ST) & (T) & 1));    \
    const float csr = side ? mB.z : mA.x, csi = side ? mB.w : mA.y;           \
    const float cpr = side ? mB.x : mA.z, cpi = side ? mB.y : mA.w;           \
    nr[T] = csr * ar[T] - csi * ai[T] + cpr * apr - cpi * api;                \
    ni[T] = csr * ai[T] + csi * ar[T] + cpr * api + cpi * apr; }

#define GGATE(GI, GM, TM, SG, ST) {                                           \
    const float4 mA = gw[GI][0], mB = gw[GI][1];                              \
    const int pg = (((SG) >> 1) & b1w) ^ ((SG) & b0w & 1);                    \
    float nr[4], ni[4];                                                       \
    GSLOT(0, GM, TM, SG, ST) GSLOT(1, GM, TM, SG, ST)                         \
    GSLOT(2, GM, TM, SG, ST) GSLOT(3, GM, TM, SG, ST)                         \
    ar[0] = nr[0]; ai[0] = ni[0]; ar[1] = nr[1]; ai[1] = ni[1];               \
    ar[2] = nr[2]; ai[2] = ni[2]; ar[3] = nr[3]; ai[3] = ni[3]; }

__global__ void __launch_bounds__(128, 1)
quanv_hybrid_kernel(const float* __restrict__ x,
                    const float* __restrict__ wq,    // [2,2,4,3]
                    const float* __restrict__ wfc,   // [3,3,1,3]
                    const float* __restrict__ Wout,  // [10,1]
                    const float* __restrict__ bout,  // [10]
                    float* __restrict__ out,         // [B,10]
                    int B)
{
    // Per-warp private copies: no cross-warp synchronization anywhere.
    __shared__ float4 gmw[4][25][2];
    __shared__ float  wobw[4][20];

    const int tid  = threadIdx.x;
    const int wid  = tid >> 5;
    const int lane = tid & 31;
    const int g    = tid & 3;
    const int s    = blockIdx.x * 32 + (tid >> 2);
    const int scl  = (s < B) ? s : (B - 1);

    float4 (*gw)[2] = gmw[wid];
    float*  wob     = wobw[wid];

    // Sample pixel first (cold-miss latency overlaps prologue).
    // Lane g -> wire g angle: patch 0 offsets {0,1,28,29}.
    const float pix = x[(size_t)scl * 784 + ((g & 1) + 28 * (g >> 1))];

    // ---- per-warp prologue ----
    if (lane < 25) {
        const float* p = (lane < 16) ? (wq + lane * 3) : (wfc + (lane - 16) * 3);
        rot_mat_fast(p[0], p[1], p[2], gw[lane]);
    } else if (lane < 31) {
        const int q_   = lane - 25;        // 0..5
        const int half = (q_ >= 3);        // 0 = Wout, 1 = bout
        const int part = q_ - half * 3;
        const float* src = half ? bout : Wout;
        float* dst = wob + half * 10;
        if (part < 2) {
            float4 v = *(const float4*)(src + part * 4);
            dst[part * 4 + 0] = v.x; dst[part * 4 + 1] = v.y;
            dst[part * 4 + 2] = v.z; dst[part * 4 + 3] = v.w;
        } else {
            float2 v = *(const float2*)(src + 8);
            dst[8] = v.x; dst[9] = v.y;
        }
    }

    float cg_, sg_;
    __sincosf(0.5f * pix, &sg_, &cg_);   // RX|0> = (cos t/2, -i sin t/2)

    // Layout: lane bits (b1w,b0w) = (wire0,wire3); slot bits = (wire1,wire2)
    const int b1w = (g >> 1) & 1;
    const int b0w = g & 1;

    __syncwarp();   // own warp's gate matrices + weights visible

    // ---- L0 fold: per-wire spinor u = Rot_g RX(th_g)|0> (lane g = wire g) ----
    //   u0 = m00*c + m01*(-i s) ; u1 = m10*c + m11*(-i s)
    float u0r_, u0i_, u1r_, u1i_;
    {
        const float4 mA = gw[g][0], mB = gw[g][1];
        u0r_ = mA.x * cg_ + mA.w * sg_;
        u0i_ = mA.y * cg_ - mA.z * sg_;
        u1r_ = mB.x * cg_ + mB.w * sg_;
        u1i_ = mB.y * cg_ - mB.z * sg_;
    }
    // broadcast all wires' spinors within the 4-lane group (one stage)
    float w0r[4], w0i[4], w1r[4], w1i[4];
#pragma unroll
    for (int w = 0; w < 4; w++) {
        w0r[w] = SH4(u0r_, w); w0i[w] = SH4(u0i_, w);
        w1r[w] = SH4(u1r_, w); w1i[w] = SH4(u1i_, w);
    }

    // product state after L0: amp(i) = u_w0[b1w] * u_w1[tb1] * u_w2[tb0] * u_w3[b0w]
    float ar[4], ai[4];
    {
        const float e0r = b1w ? w1r[0] : w0r[0], e0i = b1w ? w1i[0] : w0i[0];
        const float e3r = b0w ? w1r[3] : w0r[3], e3i = b0w ? w1i[3] : w0i[3];
        const float fr = e0r * e3r - e0i * e3i;
        const float fi = e0r * e3i + e0i * e3r;
#pragma unroll
        for (int T = 0; T < 4; T++) {
            const int tb1 = T >> 1, tb0 = T & 1;
            const float h1r = tb1 ? w1r[1] : w0r[1], h1i = tb1 ? w1i[1] : w0i[1];
            const float h2r = tb0 ? w1r[2] : w0r[2], h2i = tb0 ? w1i[2] : w0i[2];
            const float hr = h1r * h2r - h1i * h2i;
            const float hi = h1r * h2i + h1i * h2r;
            ar[T] = fr * hr - fi * hi;
            ai[T] = fr * hi + fi * hr;
        }
    }

    // ---- independent stream: V = fm[24]..fm[16] product + gate-14 constants ----
    float v0r = 1.f, v0i = 0.f, v1r = 0.f, v1i = 0.f;
    float q0r = 0.f, q0i = 0.f, q1r = 1.f, q1i = 0.f;
#pragma unroll
    for (int gi = 16; gi < 25; gi++) {
        const float4 mA = gw[gi][0];
        const float4 mB = gw[gi][1];
        float n0r = mA.x*v0r - mA.y*v0i + mA.z*v1r - mA.w*v1i;
        float n0i = mA.x*v0i + mA.y*v0r + mA.z*v1i + mA.w*v1r;
        float n1r = mB.x*v0r - mB.y*v0i + mB.z*v1r - mB.w*v1i;
        float n1i = mB.x*v0i + mB.y*v0r + mB.z*v1i + mB.w*v1r;
        v0r = n0r; v0i = n0i; v1r = n1r; v1i = n1i;
        float m0r = mA.x*q0r - mA.y*q0i + mA.z*q1r - mA.w*q1i;
        float m0i = mA.x*q0i + mA.y*q0r + mA.z*q1i + mA.w*q1r;
        float m1r = mB.x*q0r - mB.y*q0i + mB.z*q1r - mB.w*q1i;
        float m1i = mB.x*q0i + mB.y*q0r + mB.z*q1i + mB.w*q1r;
        q0r = m0r; q0i = m0i; q1r = m1r; q1i = m1i;
    }
    const float alpha = (v0r*v0r + v0i*v0i) - (v1r*v1r + v1i*v1i);
    const float beta  = (v0r*q0i - v0i*q0r) - (v1r*q1i - v1i*q1r);

    // gate-14 measurement-fold constants: K = |m00|^2-|m10|^2,
    // W = conj(m00)m01 - conj(m10)m11
    float K14, W14r, W14i;
    {
        const float4 mA = gw[14][0], mB = gw[14][1];
        K14  = (mA.x*mA.x + mA.y*mA.y) - (mB.x*mB.x + mB.y*mB.y);
        W14r = (mA.x*mA.z + mA.y*mA.w) - (mB.x*mB.z + mB.y*mB.w);
        W14i = (mA.x*mA.w - mA.y*mA.z) - (mB.x*mB.w - mB.y*mB.z);
    }

    // ---- 10 conjugated rotations (gates 4..13; masks validated R8) ----
    GGATE( 4, 2, 2, 1, 3)
    GGATE( 5, 0, 3, 2, 2)
    GGATE( 6, 1, 1, 2, 3)
    GGATE( 7, 3, 2, 3, 3)
    GGATE( 8, 3, 3, 2, 3)
    GGATE( 9, 3, 1, 3, 3)
    GGATE(10, 2, 2, 3, 0)
    GGATE(11, 0, 3, 1, 1)
    GGATE(12, 0, 2, 1, 2)
    GGATE(13, 1, 3, 1, 0)

    // ---- measurement with gate 14 folded (mu: lane^2, slot^1; gate 15 is
    //      sector-preserving -> identity for <Z0>) ----
    // K-term: K * signed sum of |amp|^2 (sign by b1w)
    float zs = ar[0]*ar[0] + ai[0]*ai[0] + ar[1]*ar[1] + ai[1]*ai[1]
             + ar[2]*ar[2] + ai[2]*ai[2] + ar[3]*ar[3] + ai[3]*ai[3];
    zs = b1w ? -zs : zs;
    // W-term: pairs (i: b1w=0, slot T) <-> (j: lane^2, slot T^1)
    float crr = 0.f, cri = 0.f;
#pragma unroll
    for (int T = 0; T < 4; T++) {
        const float pr = SHX(ar[T ^ 1], 2);
        const float pi = SHX(ai[T ^ 1], 2);
        crr += ar[T]*pr + ai[T]*pi;   // Re(conj(a_i) a_j)
        cri += ar[T]*pi - ai[T]*pr;   // Im(conj(a_i) a_j)
    }
    float part = K14 * zs + (b1w ? 0.f : 2.f * (W14r * crr - W14i * cri));
    part += SHX(part, 1);
    part += SHX(part, 2);
    const float ez = part;

    // ---- collapsed FC tail: q = alpha*cos(ez) + beta*sin(ez) ----
    float ce, se;
    __sincosf(ez, &se, &ce);
    const float q = alpha * ce + beta * se;

    // ---- Linear(1,10) + log_softmax; exps split across the 4 lanes ----
    float lg[10];
#pragma unroll
    for (int k = 0; k < 10; k++) lg[k] = fmaf(q, wob[k], wob[10 + k]);
    float pse = 0.f;
#pragma unroll
    for (int k = 0; k < 3; k++) {
        int idx = g + 4 * k;
        if (idx < 10) pse += __expf(lg[idx]);
    }
    pse += SHX(pse, 1);
    pse += SHX(pse, 2);
    const float off = __logf(pse);

    if (s < B) {
        float2* ob = (float2*)(out + (size_t)s * 10);   // 40B rows, 8B aligned
        ob[g] = make_float2(lg[2 * g] - off, lg[2 * g + 1] - off);
        if (g == 0) ob[4] = make_float2(lg[8] - off, lg[9] - off);
    }
}

extern "C" void kernel_launch(void* const* d_in, const int* in_sizes, int n_in,
                              void* d_out, int out_size) {
    const float* x    = (const float*)d_in[0];   // [B,784]
    const float* wq   = (const float*)d_in[1];   // [2,2,4,3]
    const float* wfc  = (const float*)d_in[2];   // [3,3,1,3]
    const float* Wout = (const float*)d_in[3];   // [10,1]
    const float* bout = (const float*)d_in[4];   // [10]
    float* out = (float*)d_out;                  // [B,10]

    int B = in_sizes[0] / 784;
    int blocks = (B + 31) / 32;                  // 32 samples per 128-thread block
    quanv_hybrid_kernel<<<blocks, 128>>>(x, wq, wfc, Wout, bout, out, B);
}